// round 7
// baseline (speedup 1.0000x reference)
#include <cuda_runtime.h>
#include <cstdint>

// ===========================================================================
// TT-linear via rank-64 bottleneck:  W = A(4096x64) @ B(64x4096)
//   t = x @ B^T      (mma.sync tf32, split-K=4, 3-stage cp.async ring, 4 CTA/SM)
//   y = t @ A^T + b  (mma.sync tf32, K=64 one-shot, 128x128 tiles, 2 CTA/SM)
// ===========================================================================
__device__ __align__(256) float g_A[4096 * 64];     // A (out, r)  tf32-rounded
__device__ __align__(256) float g_G45[64 * 256];    // fold(core4,core5)
__device__ __align__(256) float g_B[64 * 4096];     // B (r, in)   tf32-rounded
__device__ __align__(256) float g_T[4][8192 * 64];  // split-K partials of t

// ---------------- helpers ---------------------------------------------------
__device__ __forceinline__ uint32_t smem_u32(const void* p) {
    uint32_t a;
    asm("{ .reg .u64 t; cvta.to.shared.u64 t, %1; cvt.u32.u64 %0, t; }" : "=r"(a) : "l"(p));
    return a;
}
__device__ __forceinline__ float rna(float v) {
    uint32_t r; asm("cvt.rna.tf32.f32 %0, %1;" : "=r"(r) : "f"(v));
    return __uint_as_float(r);
}
__device__ __forceinline__ void cp16(uint32_t dst, const void* src) {
    asm volatile("cp.async.cg.shared.global [%0], [%1], 16;" :: "r"(dst), "l"(src));
}
#define CP_COMMIT() asm volatile("cp.async.commit_group;" ::: "memory")
#define CP_WAIT1()  asm volatile("cp.async.wait_group 1;" ::: "memory")

// D += A * B   (m16n8k8, tf32 inputs in b32 regs, f32 accum)
__device__ __forceinline__ void mma8(float* c, const uint32_t* a, const uint32_t* b) {
    asm volatile(
        "mma.sync.aligned.m16n8k8.row.col.f32.tf32.tf32.f32 "
        "{%0,%1,%2,%3}, {%4,%5,%6,%7}, {%8,%9}, {%0,%1,%2,%3};"
        : "+f"(c[0]), "+f"(c[1]), "+f"(c[2]), "+f"(c[3])
        : "r"(a[0]), "r"(a[1]), "r"(a[2]), "r"(a[3]), "r"(b[0]), "r"(b[1]));
}

// ---------------------------------------------------------------------------
// Folds. Core shapes: G0(1,16,64) G1..G4(64,16,64) G5(64,16,1).
// ---------------------------------------------------------------------------
__global__ __launch_bounds__(256) void fold12_kernel(const float* __restrict__ G0,
                                                     const float* __restrict__ G1,
                                                     const float* __restrict__ G2) {
    __shared__ float w01row[64];
    const int b = blockIdx.x;
    const int r = b >> 2, s0 = r >> 4, s1 = r & 15;
    const int tid = threadIdx.x;
    if (tid < 64) {
        float s = 0.f;
#pragma unroll
        for (int r1 = 0; r1 < 64; ++r1)
            s += G0[s0 * 64 + r1] * G1[r1 * 1024 + s1 * 64 + tid];
        w01row[tid] = s;
    }
    __syncthreads();
    const int c = (b & 3) * 256 + tid;
    float a0 = 0.f, a1 = 0.f, a2 = 0.f, a3 = 0.f;
#pragma unroll
    for (int r2 = 0; r2 < 64; r2 += 4) {
        a0 += w01row[r2]     * G2[r2 * 1024 + c];
        a1 += w01row[r2 + 1] * G2[(r2 + 1) * 1024 + c];
        a2 += w01row[r2 + 2] * G2[(r2 + 2) * 1024 + c];
        a3 += w01row[r2 + 3] * G2[(r2 + 3) * 1024 + c];
    }
    g_A[(size_t)r * 1024 + c] = rna((a0 + a1) + (a2 + a3));
}

__global__ void foldG45_kernel(const float* __restrict__ G4, const float* __restrict__ G5) {
    int i = blockIdx.x * 256 + threadIdx.x;       // 16384: G45[r4][(s4,s5)]
    int r4 = i >> 8, s4 = (i >> 4) & 15, s5 = i & 15;
    float s = 0.f;
#pragma unroll
    for (int r5 = 0; r5 < 64; ++r5) s += G4[r4 * 1024 + s4 * 64 + r5] * G5[r5 * 16 + s5];
    g_G45[i] = s;
}

// B[(r3,s3)][(s4,s5)]: flat (1024,256) == (64,4096) row-major.
__global__ __launch_bounds__(256) void foldB_kernel(const float* __restrict__ G3) {
    const int b = blockIdx.x;       // output row 0..1023
    const int c = threadIdx.x;      // output col 0..255
    float a0 = 0.f, a1 = 0.f, a2 = 0.f, a3 = 0.f;
#pragma unroll
    for (int r4 = 0; r4 < 64; r4 += 4) {
        a0 += G3[b * 64 + r4]     * g_G45[r4 * 256 + c];
        a1 += G3[b * 64 + r4 + 1] * g_G45[(r4 + 1) * 256 + c];
        a2 += G3[b * 64 + r4 + 2] * g_G45[(r4 + 2) * 256 + c];
        a3 += G3[b * 64 + r4 + 3] * g_G45[(r4 + 3) * 256 + c];
    }
    g_B[(size_t)b * 256 + c] = rna((a0 + a1) + (a2 + a3));
}

// ---------------------------------------------------------------------------
// GEMM1: t[n,r] = sum_k x[n,k]*B[r,k].  M=8192 N=64 K=4096, split-K=4.
// grid (128,4) = 512 CTAs. CTA 64 tok x 64 r, 256 threads, 8 warps 4x2,
// warp tile 16x32. K chunks of 32, 3-stage cp.async ring (18432 B/stage).
// Stage: x 64 rows x 144B (9216) then B 64 x 144B (9216).
// ---------------------------------------------------------------------------
__global__ __launch_bounds__(256) void gemm1_kernel(const float* __restrict__ x) {
    extern __shared__ char sm[];
    const uint32_t sb = smem_u32(sm);
    const int tid = threadIdx.x;
    const int warp = tid >> 5, lane = tid & 31;
    const int wm = warp >> 1, wn = warp & 1;      // warp origin (wm*16, wn*32)
    const int tok0 = blockIdx.x * 64;
    const int kbase = blockIdx.y * 1024;
    const int qr = (tid & 7) * 4;                 // float col within 32-chunk
    const int row0 = tid >> 3;                    // 0..31

    float acc[4][4];
#pragma unroll
    for (int b = 0; b < 4; ++b)
#pragma unroll
        for (int c = 0; c < 4; ++c) acc[b][c] = 0.f;

    auto issue = [&](int chunk, int s) {
        int kc = kbase + chunk * 32;
        uint32_t xd = sb + s * 18432;
        uint32_t bd = xd + 9216;
#pragma unroll
        for (int l = 0; l < 2; ++l) {
            int r = row0 + 32 * l;
            cp16(xd + (uint32_t)(r * 144 + qr * 4), &x[(size_t)(tok0 + r) * 4096 + kc + qr]);
            cp16(bd + (uint32_t)(r * 144 + qr * 4), &g_B[(size_t)r * 4096 + kc + qr]);
        }
    };

    issue(0, 0); CP_COMMIT();
    issue(1, 1); CP_COMMIT();

    const int lr = lane >> 2, lc = lane & 3;
    int stage = 0;
    for (int i = 0; i < 32; ++i) {
        CP_WAIT1();
        __syncthreads();
        if (i + 2 < 32) issue(i + 2, (stage + 2) % 3);
        CP_COMMIT();    // empty group at tail keeps wait_group 1 uniform

        const float* xs = reinterpret_cast<const float*>(sm + stage * 18432);
        const float* bs = reinterpret_cast<const float*>(sm + stage * 18432 + 9216);
#pragma unroll
        for (int k8 = 0; k8 < 4; ++k8) {
            const int kk = k8 * 8 + lc;
            uint32_t af[4], bf[4][2];
            {
                int r = wm * 16 + lr;
                af[0] = __float_as_uint(xs[r * 36 + kk]);
                af[1] = __float_as_uint(xs[(r + 8) * 36 + kk]);
                af[2] = __float_as_uint(xs[r * 36 + kk + 4]);
                af[3] = __float_as_uint(xs[(r + 8) * 36 + kk + 4]);
            }
#pragma unroll
            for (int nt = 0; nt < 4; ++nt) {
                int n = wn * 32 + nt * 8 + lr;
                bf[nt][0] = __float_as_uint(bs[n * 36 + kk]);
                bf[nt][1] = __float_as_uint(bs[n * 36 + kk + 4]);
            }
#pragma unroll
            for (int nt = 0; nt < 4; ++nt) mma8(acc[nt], af, bf[nt]);
        }
        stage = (stage + 1) % 3;
    }

    // epilogue: raw fp32 partials (summed+rounded in gemm2)
    float* tp = g_T[blockIdx.y];
#pragma unroll
    for (int nt = 0; nt < 4; ++nt)
#pragma unroll
        for (int h = 0; h < 2; ++h) {
            int r = tok0 + wm * 16 + lr + 8 * h;
            int c = wn * 32 + nt * 8 + 2 * lc;
            *reinterpret_cast<float2*>(&tp[(size_t)r * 64 + c]) =
                make_float2(acc[nt][2 * h], acc[nt][2 * h + 1]);
        }
}

// ---------------------------------------------------------------------------
// GEMM2: y[n,o] = sum_r t[n,r]*A[o,r] + b[o].  M=8192 N=4096 K=64.
// grid (64,32) = 2048 CTAs. CTA 128 tok x 128 out, 256 threads,
// 8 warps 4x2, warp tile 32x64. K=64 one-shot (rows padded to 68 floats).
// 2 CTAs/SM (69.6 KB smem, <=128 regs).
// ---------------------------------------------------------------------------
__global__ __launch_bounds__(256, 2) void gemm2_kernel(const float* __restrict__ bias,
                                                       float* __restrict__ y) {
    extern __shared__ char sm[];
    float* st = reinterpret_cast<float*>(sm);                 // [128][68]
    float* sa = reinterpret_cast<float*>(sm) + 128 * 68;      // [128][68]
    const int tid = threadIdx.x;
    const int warp = tid >> 5, lane = tid & 31;
    const int wm = warp >> 1, wn = warp & 1;      // warp origin (wm*32, wn*64)
    const int tok0 = blockIdx.x * 128, out0 = blockIdx.y * 128;

    // t tile: reduce 4 split-K partials, round to tf32. 128x64 = 2048 f4 slots.
#pragma unroll
    for (int l = 0; l < 8; ++l) {
        int s = tid + 256 * l, row = s >> 4, q = (s & 15) * 4;
        size_t off = (size_t)(tok0 + row) * 64 + q;
        float4 v0 = *reinterpret_cast<const float4*>(&g_T[0][off]);
        float4 v1 = *reinterpret_cast<const float4*>(&g_T[1][off]);
        float4 v2 = *reinterpret_cast<const float4*>(&g_T[2][off]);
        float4 v3 = *reinterpret_cast<const float4*>(&g_T[3][off]);
        st[row * 68 + q + 0] = rna((v0.x + v1.x) + (v2.x + v3.x));
        st[row * 68 + q + 1] = rna((v0.y + v1.y) + (v2.y + v3.y));
        st[row * 68 + q + 2] = rna((v0.z + v1.z) + (v2.z + v3.z));
        st[row * 68 + q + 3] = rna((v0.w + v1.w) + (v2.w + v3.w));
    }
    // A tile: 128x64 = 2048 f4 slots.
#pragma unroll
    for (int l = 0; l < 8; ++l) {
        int s = tid + 256 * l, row = s >> 4, q = (s & 15) * 4;
        *reinterpret_cast<float4*>(&sa[row * 68 + q]) =
            *reinterpret_cast<const float4*>(&g_A[(size_t)(out0 + row) * 64 + q]);
    }
    __syncthreads();

    float acc[2][8][4];
#pragma unroll
    for (int a = 0; a < 2; ++a)
#pragma unroll
        for (int b = 0; b < 8; ++b)
#pragma unroll
            for (int c = 0; c < 4; ++c) acc[a][b][c] = 0.f;

    const int lr = lane >> 2, lc = lane & 3;
#pragma unroll
    for (int k8 = 0; k8 < 8; ++k8) {
        const int kk = k8 * 8 + lc;
        uint32_t af[2][4], bf[8][2];
#pragma unroll
        for (int mt = 0; mt < 2; ++mt) {
            int r = wm * 32 + mt * 16 + lr;
            af[mt][0] = __float_as_uint(st[r * 68 + kk]);
            af[mt][1] = __float_as_uint(st[(r + 8) * 68 + kk]);
            af[mt][2] = __float_as_uint(st[r * 68 + kk + 4]);
            af[mt][3] = __float_as_uint(st[(r + 8) * 68 + kk + 4]);
        }
#pragma unroll
        for (int nt = 0; nt < 8; ++nt) {
            int n = wn * 64 + nt * 8 + lr;
            bf[nt][0] = __float_as_uint(sa[n * 68 + kk]);
            bf[nt][1] = __float_as_uint(sa[n * 68 + kk + 4]);
        }
#pragma unroll
        for (int mt = 0; mt < 2; ++mt)
#pragma unroll
            for (int nt = 0; nt < 8; ++nt) mma8(acc[mt][nt], af[mt], bf[nt]);
    }

    float2 bv[8];
#pragma unroll
    for (int nt = 0; nt < 8; ++nt)
        bv[nt] = *reinterpret_cast<const float2*>(&bias[out0 + wn * 64 + nt * 8 + 2 * lc]);

#pragma unroll
    for (int mt = 0; mt < 2; ++mt)
#pragma unroll
        for (int h = 0; h < 2; ++h) {
            int r = tok0 + wm * 32 + mt * 16 + lr + 8 * h;
            float* yr = y + (size_t)r * 4096 + out0 + wn * 64;
#pragma unroll
            for (int nt = 0; nt < 8; ++nt) {
                *reinterpret_cast<float2*>(&yr[nt * 8 + 2 * lc]) =
                    make_float2(acc[mt][nt][2 * h] + bv[nt].x,
                                acc[mt][nt][2 * h + 1] + bv[nt].y);
            }
        }
}

// ---------------------------------------------------------------------------
// Launch
// ---------------------------------------------------------------------------
extern "C" void kernel_launch(void* const* d_in, const int* in_sizes, int n_in,
                              void* d_out, int out_size) {
    const float* core[6] = {nullptr, nullptr, nullptr, nullptr, nullptr, nullptr};
    const float* x = nullptr;
    const float* bias = nullptr;
    int c64 = 1;
    for (int i = 0; i < n_in; ++i) {
        int sz = in_sizes[i];
        const float* p = reinterpret_cast<const float*>(d_in[i]);
        if (sz == 8192 * 4096) x = p;
        else if (sz == 4096) bias = p;
        else if (sz == 65536) { if (c64 <= 4) core[c64++] = p; }
        else if (sz == 1024) { if (!core[0]) core[0] = p; else core[5] = p; }
    }
    float* y = reinterpret_cast<float*>(d_out);

    const int g1_smem = 3 * 18432;                  // 55296 -> 4 CTAs/SM
    const int g2_smem = 2 * 128 * 68 * 4;           // 69632 -> 2 CTAs/SM
    cudaFuncSetAttribute(gemm1_kernel, cudaFuncAttributeMaxDynamicSharedMemorySize, g1_smem);
    cudaFuncSetAttribute(gemm2_kernel, cudaFuncAttributeMaxDynamicSharedMemorySize, g2_smem);
    cudaFuncSetAttribute(gemm1_kernel, cudaFuncAttributePreferredSharedMemoryCarveout, 100);
    cudaFuncSetAttribute(gemm2_kernel, cudaFuncAttributePreferredSharedMemoryCarveout, 100);

    foldG45_kernel<<<64, 256>>>(core[4], core[5]);
    foldB_kernel<<<1024, 256>>>(core[3]);
    fold12_kernel<<<1024, 256>>>(core[0], core[1], core[2]);
    gemm1_kernel<<<dim3(128, 4), 256, g1_smem>>>(x);
    gemm2_kernel<<<dim3(64, 32), 256, g2_smem>>>(bias, y);
}